// round 9
// baseline (speedup 1.0000x reference)
#include <cuda_runtime.h>
#include <cuda_fp16.h>
#include <cstdint>

#define NB 4096
#define NT 32               // 32x32 grid of 128x128 tiles
#define NTILES 528          // upper-triangle tiles
#define NUNITS 2112         // 4 x (128 rows x 32 cols) units per tile
#define FMA_STOP 1760       // fma CTAs stop pulling near the tail

// ---------------- device scratch (static: no allocation allowed) ----------------
// C row (256 fp16, 512B): [x | -2m | 1/v | m/v], x = v + m^2
// "D" row = C rotated by 128 cols; phase p of D = phase 1-p of C (256B phases).
__device__ __half g_C[(size_t)NB * 256];
__device__ float  g_A8[NB];    // 0.125*a_i - 8
__device__ float  g_P8[NB];    // 0.125*p_i
__device__ float  g_Q[NB];     // 1/(p_i + 1e-8)
__device__ double g_pos, g_neg;
__device__ unsigned g_arrive = 0, g_done = 0, g_ticket = 0;
__device__ volatile unsigned g_release = 0;

static __device__ __forceinline__ uint32_t smem_u32(const void* p) {
    uint32_t a;
    asm("{ .reg .u64 t; cvta.to.shared.u64 t, %1; cvt.u32.u64 %0, t; }" : "=r"(a) : "l"(p));
    return a;
}
static __device__ __forceinline__ float frcp(float x) {
    float r; asm("rcp.approx.f32 %0, %1;" : "=f"(r) : "f"(x)); return r;
}
static __device__ __forceinline__ float ftanh(float x) {
    float r; asm("tanh.approx.f32 %0, %1;" : "=f"(r) : "f"(x)); return r;
}
static __device__ __forceinline__ void cpa16(uint32_t dst, const void* src) {
    asm volatile("cp.async.ca.shared.global [%0], [%1], 16;" :: "r"(dst), "l"(src));
}

// smem: A phase-tile 128x128 fp16 (32KB, XOR-swizzled 16B chunks, pitch 256B),
//       B phase-tile 32x128 fp16 (8KB), params, scratch
#define AS_OFF 0
#define BS_OFF 32768
#define PAR_OFF 40960
#define RED_OFF 43520
#define SMEM_BYTES 43584

// ---- stage one K=128 phase: A rows [Ibase,+128), B rows [colBase,+32) ----
static __device__ __forceinline__ void stage_phase(
    uint32_t sbase, const char* baseI, const char* baseJ, int phase, int tid)
{
    int pa = phase * 256, pb = 256 - phase * 256;   // D phase p = C phase 1-p
    #pragma unroll
    for (int p = 0; p < 16; p++) {
        int idx = tid + p * 128, r = idx >> 4, c16 = idx & 15;
        cpa16(sbase + AS_OFF + r * 256 + ((c16 ^ (r & 7)) << 4),
              baseI + r * 512 + pa + c16 * 16);
    }
    #pragma unroll
    for (int p = 0; p < 4; p++) {
        int idx = tid + p * 128, r = idx >> 4, c16 = idx & 15;
        cpa16(sbase + BS_OFF + r * 256 + ((c16 ^ (r & 7)) << 4),
              baseJ + r * 512 + pb + c16 * 16);
    }
    asm volatile("cp.async.commit_group;" ::: "memory");
}

// ---- tensor: one K=128 phase of the 128x32 GEMM (warp tile 64x16) ----
static __device__ __forceinline__ void gemm_phase(
    uint32_t csA, uint32_t csB, int lane, int warp_m, int warp_n,
    uint32_t (&acc)[4][2][2])
{
    #pragma unroll
    for (int s = 0; s < 8; s++) {
        uint32_t af[4][4];
        #pragma unroll
        for (int mi = 0; mi < 4; mi++) {
            int r = warp_m * 64 + mi * 16 + (lane & 15);
            int c16 = 2 * s + (lane >> 4);
            uint32_t addr = csA + r * 256 + ((c16 ^ (r & 7)) << 4);
            asm volatile("ldmatrix.sync.aligned.m8n8.x4.shared.b16 {%0,%1,%2,%3}, [%4];"
                         : "=r"(af[mi][0]), "=r"(af[mi][1]), "=r"(af[mi][2]), "=r"(af[mi][3])
                         : "r"(addr));
        }
        #pragma unroll
        for (int ni = 0; ni < 2; ni++) {
            int r = warp_n * 16 + ni * 8 + (lane & 7);
            int c16 = 2 * s + ((lane >> 3) & 1);
            uint32_t addr = csB + r * 256 + ((c16 ^ (r & 7)) << 4);
            uint32_t b0, b1;
            asm volatile("ldmatrix.sync.aligned.m8n8.x2.shared.b16 {%0,%1}, [%2];"
                         : "=r"(b0), "=r"(b1) : "r"(addr));
            #pragma unroll
            for (int mi = 0; mi < 4; mi++) {
                asm volatile(
                    "mma.sync.aligned.m16n8k16.row.col.f16.f16.f16.f16 "
                    "{%0,%1}, {%2,%3,%4,%5}, {%6,%7}, {%0,%1};"
                    : "+r"(acc[mi][ni][0]), "+r"(acc[mi][ni][1])
                    : "r"(af[mi][0]), "r"(af[mi][1]), "r"(af[mi][2]), "r"(af[mi][3]),
                      "r"(b0), "r"(b1));
            }
        }
    }
}

// ---- fma: one K=128 phase; lane = row tid, 32 cols; fp16x2 acc + fp32 spill ----
static __device__ __forceinline__ void fma_phase(
    const char* smem, int tid, float (&acc32)[32])
{
    uint32_t acc2[32];
    #pragma unroll
    for (int j = 0; j < 32; j++) acc2[j] = 0u;
    #pragma unroll 1
    for (int cc = 0; cc < 2; cc++) {
        #pragma unroll
        for (int c8 = 0; c8 < 8; c8++) {
            int c = cc * 8 + c8;
            uint4 av = *(const uint4*)(smem + AS_OFF + tid * 256 + ((c ^ (tid & 7)) << 4));
            __half2 a0 = *(__half2*)&av.x, a1 = *(__half2*)&av.y;
            __half2 a2 = *(__half2*)&av.z, a3 = *(__half2*)&av.w;
            #pragma unroll
            for (int j = 0; j < 32; j++) {
                uint4 bv = *(const uint4*)(smem + BS_OFF + j * 256 + ((c ^ (j & 7)) << 4));
                __half2 t = *(__half2*)&acc2[j];
                t = __hfma2(a0, *(__half2*)&bv.x, t);
                t = __hfma2(a1, *(__half2*)&bv.y, t);
                t = __hfma2(a2, *(__half2*)&bv.z, t);
                t = __hfma2(a3, *(__half2*)&bv.w, t);
                acc2[j] = *(uint32_t*)&t;
            }
        }
        #pragma unroll
        for (int j = 0; j < 32; j++) {      // spill every 64 K-halves
            float2 f = __half22float2(*(__half2*)&acc2[j]);
            acc32[j] += f.x + f.y;
            acc2[j] = 0u;
        }
    }
}

static __device__ __forceinline__ void decode_tile(int ft, int& I, int& J) {
    I = 0;
    while (ft >= NT - I) { ft -= NT - I; I++; }
    J = I + ft;
}

__global__ void __launch_bounds__(128, 4) mega_kernel(
    const float* __restrict__ mu, const float* __restrict__ var,
    const int* __restrict__ labels, float* __restrict__ out)
{
    extern __shared__ char smem[];
    uint32_t sbase = smem_u32(smem);
    int tid = threadIdx.x, lane = tid & 31, wid = tid >> 5;

    // ================= phase 0: prep =================
    for (int row0 = blockIdx.x * 8; row0 < NB; row0 += gridDim.x * 8) {
        int row = row0 + (tid >> 4), l16 = tid & 15;
        float4 m4 = ((const float4*)(mu  + (size_t)row * 64))[l16];
        float4 v4 = ((const float4*)(var + (size_t)row * 64))[l16];
        float m[4] = {m4.x, m4.y, m4.z, m4.w};
        float v[4] = {v4.x, v4.y, v4.z, v4.w};
        float x[4], n2m[4], iv[4], w[4];
        float pv = 1.0f, av = 0.0f;
        #pragma unroll
        for (int d = 0; d < 4; d++) {
            iv[d]  = frcp(v[d]);
            x[d]   = v[d] + m[d] * m[d];
            n2m[d] = -2.0f * m[d];
            w[d]   = m[d] * iv[d];
            pv *= v[d];
            av = fmaf(m[d] * m[d], iv[d], av);
        }
        uint2* crow = (uint2*)(g_C + (size_t)row * 256);
        const float* blocks[4] = {x, n2m, iv, w};
        #pragma unroll
        for (int b = 0; b < 4; b++) {
            const float* s = blocks[b];
            __half2 h2[2] = {__floats2half2_rn(s[0], s[1]), __floats2half2_rn(s[2], s[3])};
            crow[b * 16 + l16] = *(uint2*)h2;
        }
        #pragma unroll
        for (int off = 1; off < 16; off <<= 1) {
            pv *= __shfl_xor_sync(0xffffffffu, pv, off);
            av += __shfl_xor_sync(0xffffffffu, av, off);
        }
        if (l16 == 0) {
            g_A8[row] = 0.125f * av - 8.0f;
            g_P8[row] = 0.125f * pv;
            g_Q[row]  = frcp(pv + 1e-8f);
        }
    }

    // ================= device-wide barrier =================
    __syncthreads();
    if (tid == 0) {
        unsigned target = g_release + 1;
        __threadfence();
        unsigned a = atomicAdd(&g_arrive, 1);
        if (a == gridDim.x - 1) {
            g_arrive = 0;
            g_pos = 0.0; g_neg = 0.0;
            g_ticket = gridDim.x;
            __threadfence();
            atomicAdd((unsigned*)&g_release, 1);
        } else {
            while (g_release < target) __nanosleep(64);
        }
        __threadfence();
    }
    __syncthreads();

    // ================= phase 1: unit loop (128 rows x 32 cols per unit) =================
    float* spAI = (float*)(smem + PAR_OFF);
    float* spPI = spAI + 128;
    float* spQI = spPI + 128;
    int*   spLI = (int*)(spQI + 128);
    float* spAJ = (float*)(spLI + 128);   // 32 entries
    float* spPJ = spAJ + 32;
    float* spQJ = spPJ + 32;
    int*   spLJ = (int*)(spQJ + 32);
    float* red  = (float*)(smem + RED_OFF);
    unsigned* tick_s = (unsigned*)(red + 8);

    uint32_t csA = sbase + AS_OFF, csB = sbase + BS_OFF;
    const bool isFma = (blockIdx.x < (gridDim.x >> 2)) && (blockIdx.x < 148);
    int warp_m = wid & 1, warp_n = wid >> 1;
    float pos = 0.0f, neg = 0.0f;
    unsigned t = blockIdx.x;

    while (t < NUNITS) {
        int I, J;
        decode_tile((int)(t >> 2), I, J);
        int q = (int)(t & 3);
        int Ibase = I * 128, colBase = J * 128 + q * 32;
        const char* baseI = (const char*)g_C + (size_t)Ibase * 512;
        const char* baseJ = (const char*)g_C + (size_t)colBase * 512;
        const bool diag = (I == J);

        // ---- stage phase 0 + params ----
        stage_phase(sbase, baseI, baseJ, 0, tid);
        spAI[tid] = g_A8[Ibase + tid];
        spPI[tid] = g_P8[Ibase + tid];
        spQI[tid] = g_Q[Ibase + tid];
        spLI[tid] = labels[Ibase + tid];
        if (tid < 32) {
            spAJ[tid] = g_A8[colBase + tid];
            spPJ[tid] = g_P8[colBase + tid];
            spQJ[tid] = g_Q[colBase + tid];
            spLJ[tid] = labels[colBase + tid];
        }
        asm volatile("cp.async.wait_group 0;" ::: "memory");
        __syncthreads();

        if (!isFma) {
            // =========== tensor path ===========
            uint32_t acc[4][2][2];
            #pragma unroll
            for (int mi = 0; mi < 4; mi++)
                #pragma unroll
                for (int ni = 0; ni < 2; ni++) { acc[mi][ni][0] = 0u; acc[mi][ni][1] = 0u; }

            gemm_phase(csA, csB, lane, warp_m, warp_n, acc);
            __syncthreads();
            stage_phase(sbase, baseI, baseJ, 1, tid);
            asm volatile("cp.async.wait_group 0;" ::: "memory");
            __syncthreads();
            gemm_phase(csA, csB, lane, warp_m, warp_n, acc);

            #pragma unroll
            for (int mi = 0; mi < 4; mi++) {
                #pragma unroll
                for (int k = 0; k < 2; k++) {
                    int r = warp_m * 64 + mi * 16 + (lane >> 2) + k * 8;
                    float RA = spAI[r], RP = spPI[r], RQ = spQI[r];
                    int   RL = spLI[r];
                    #pragma unroll
                    for (int ni = 0; ni < 2; ni++) {
                        __half2 hv = *reinterpret_cast<__half2*>(&acc[mi][ni][k]);
                        float2 f = __half22float2(hv);
                        int c0 = warp_n * 16 + ni * 8 + (lane & 3) * 2;
                        #pragma unroll
                        for (int e = 0; e < 2; e++) {
                            int c = c0 + e;
                            float vv = e ? f.y : f.x;
                            float s = fmaf(vv, 0.125f, RA);
                            s += spAJ[c];
                            s = fmaf(RP, spQJ[c], s);
                            s = fmaf(spPJ[c], RQ, s);
                            float sg = fmaf(ftanh(s), 0.5f, 0.5f);
                            bool count = (!diag) || (q * 32 + c > r);
                            bool same  = (RL == spLJ[c]);
                            if (count) {
                                pos += same ? sg : 0.0f;
                                neg += same ? 0.0f : sg;
                            }
                        }
                    }
                }
            }
        } else {
            // =========== HFMA2 path: lane = row tid, 32 cols ===========
            float acc32[32];
            #pragma unroll
            for (int j = 0; j < 32; j++) acc32[j] = 0.0f;

            fma_phase(smem, tid, acc32);
            __syncthreads();
            stage_phase(sbase, baseI, baseJ, 1, tid);
            asm volatile("cp.async.wait_group 0;" ::: "memory");
            __syncthreads();
            fma_phase(smem, tid, acc32);

            float RA = spAI[tid], RP = spPI[tid], RQ = spQI[tid];
            int   RL = spLI[tid];
            #pragma unroll
            for (int c = 0; c < 32; c++) {
                float s = fmaf(acc32[c], 0.125f, RA);
                s += spAJ[c];
                s = fmaf(RP, spQJ[c], s);
                s = fmaf(spPJ[c], RQ, s);
                float sg = fmaf(ftanh(s), 0.5f, 0.5f);
                bool count = (!diag) || (q * 32 + c > tid);
                bool same  = (RL == spLJ[c]);
                if (count) {
                    pos += same ? sg : 0.0f;
                    neg += same ? 0.0f : sg;
                }
            }
        }

        // ---- next ticket (fma CTAs stop near the tail) ----
        __syncthreads();
        if (tid == 0) {
            unsigned nt;
            if (isFma && g_ticket >= FMA_STOP) nt = 0xFFFFFFFFu;
            else nt = atomicAdd(&g_ticket, 1);
            *tick_s = nt;
        }
        __syncthreads();
        t = *tick_s;
    }

    // ================= final reduce + output by last CTA =================
    #pragma unroll
    for (int off = 16; off; off >>= 1) {
        pos += __shfl_xor_sync(0xffffffffu, pos, off);
        neg += __shfl_xor_sync(0xffffffffu, neg, off);
    }
    __syncthreads();
    if (lane == 0) { red[wid] = pos; red[4 + wid] = neg; }
    __syncthreads();
    if (tid == 0) {
        double P = 0.0, Nn = 0.0;
        #pragma unroll
        for (int w = 0; w < 4; w++) { P += (double)red[w]; Nn += (double)red[4 + w]; }
        atomicAdd(&g_pos, P);
        atomicAdd(&g_neg, Nn);
        __threadfence();
        unsigned d = atomicAdd(&g_done, 1);
        if (d == gridDim.x - 1) {
            double TP = 2.0 * atomicAdd(&g_pos, 0.0);
            double TN = 2.0 * atomicAdd(&g_neg, 0.0);
            const double inv = 1.0 / ((double)NB * (double)NB);
            out[0] = (float)(TP * inv);
            out[1] = (float)(TN * inv);
            out[2] = (float)TP;
            out[3] = (float)TN;
            g_done = 0;
        }
    }
}

// ---------------- launcher ----------------
extern "C" void kernel_launch(void* const* d_in, const int* in_sizes, int n_in,
                              void* d_out, int out_size) {
    (void)in_sizes; (void)n_in; (void)out_size;
    const float* mu     = (const float*)d_in[0];
    const float* var    = (const float*)d_in[1];
    const int*   labels = (const int*)d_in[2];
    float* out = (float*)d_out;

    cudaFuncSetAttribute(mega_kernel, cudaFuncAttributeMaxDynamicSharedMemorySize,
                         SMEM_BYTES);
    int occ = 0, sms = 0, dev = 0;
    cudaGetDevice(&dev);
    cudaOccupancyMaxActiveBlocksPerMultiprocessor(&occ, mega_kernel, 128, SMEM_BYTES);
    cudaDeviceGetAttribute(&sms, cudaDevAttrMultiProcessorCount, dev);
    int grid = occ * sms;
    if (grid > NUNITS) grid = NUNITS;
    if (grid < 1) grid = 1;

    mega_kernel<<<grid, 128, SMEM_BYTES>>>(mu, var, labels, out);
}